// round 13
// baseline (speedup 1.0000x reference)
#include <cuda_runtime.h>
#include <math.h>

// Problem constants
#define NB 128
#define NI 1152
#define NO 32
#define ND 16
#define KSUB 922          // ceil(0.8 * 1152)
#define CHUNKS 6
#define IPB (NI / CHUNKS) // 192 i's per block
#define IPW (IPB / 8)     // 24 i's per warp (8 warps / block)
#define MAXREJ 232        // >= NI - KSUB = 230
#define KPT 9             // keys per thread in select: 1152/128

// Scratch (no allocation allowed -> __device__ globals)
__device__ float g_num[NB * NO * ND];
__device__ float g_den[NB * NO];
__device__ float g_losses[(size_t)NB * NO * NI]; // transposed: [b][o][i]

__global__ void k_zero() {
    int idx = blockIdx.x * blockDim.x + threadIdx.x;
    if (idx < NB * NO * ND) g_num[idx] = 0.f;
    if (idx < NB * NO)      g_den[idx] = 0.f;
}

// ---------------------------------------------------------------------------
// Pass 1: n = ||u||, num = sum_i u*n, den = sum_i n  (per b,o)
// grid = NB*CHUNKS = 768 blocks ~= one full wave at 5 blocks/SM.
// ---------------------------------------------------------------------------
__global__ void __launch_bounds__(256) k_pass1(const float* __restrict__ u) {
    int b = blockIdx.x / CHUNKS;
    int chunk = blockIdx.x % CHUNKS;
    int w = threadIdx.x >> 5;
    int lane = threadIdx.x & 31;

    const float4* up = (const float4*)u + (size_t)b * NI * (NO * ND / 4);
    float acc[ND];
    float accden = 0.f;
#pragma unroll
    for (int d = 0; d < ND; d++) acc[d] = 0.f;

    int i0 = chunk * IPB + w * IPW;
#pragma unroll 2
    for (int ii = 0; ii < IPW; ii++) {
        const float4* row = up + (size_t)(i0 + ii) * (NO * ND / 4) + lane * (ND / 4);
        float4 a0 = row[0], a1 = row[1], a2 = row[2], a3 = row[3];
        float va[16] = {a0.x, a0.y, a0.z, a0.w, a1.x, a1.y, a1.z, a1.w,
                        a2.x, a2.y, a2.z, a2.w, a3.x, a3.y, a3.z, a3.w};
        float s = 0.f;
#pragma unroll
        for (int d = 0; d < 16; d++) s += va[d] * va[d];
        float n = sqrtf(s);
#pragma unroll
        for (int d = 0; d < 16; d++) acc[d] += va[d] * n;
        accden += n;
    }

    __shared__ float snum[8][NO * ND];
    __shared__ float sden[8][NO];
#pragma unroll
    for (int d = 0; d < ND; d++) snum[w][d * NO + lane] = acc[d];
    sden[w][lane] = accden;
    __syncthreads();

    for (int idx = threadIdx.x; idx < NO * ND; idx += 256) {
        int d = idx / NO, o = idx % NO;
        float s = 0.f;
#pragma unroll
        for (int ww = 0; ww < 8; ww++) s += snum[ww][idx];
        atomicAdd(&g_num[b * NO * ND + o * ND + d], s);
    }
    if (threadIdx.x < NO) {
        float s = 0.f;
#pragma unroll
        for (int ww = 0; ww < 8; ww++) s += sden[ww][threadIdx.x];
        atomicAdd(&g_den[b * NO + threadIdx.x], s);
    }
}

// ---------------------------------------------------------------------------
// Pass 2: losses[b,o,i] = -<v[b,o,:], u[b,i,o,:]>, transposed store.
// ---------------------------------------------------------------------------
__global__ void __launch_bounds__(256) k_pass2(const float* __restrict__ u) {
    __shared__ float sv[ND * NO];        // transposed: sv[d*NO + o]
    __shared__ float tile[IPB][NO + 1];  // [i_local][o], padded (192x33)
    int b = blockIdx.x / CHUNKS;
    int chunk = blockIdx.x % CHUNKS;
    for (int idx = threadIdx.x; idx < NO * ND; idx += 256) {
        int o = idx / ND, d = idx % ND;
        sv[d * NO + o] = g_num[b * NO * ND + idx] / g_den[b * NO + o];
    }
    __syncthreads();

    int w = threadIdx.x >> 5;
    int lane = threadIdx.x & 31;
    const float4* up = (const float4*)u + (size_t)b * NI * (NO * ND / 4);
    int i0 = chunk * IPB;
#pragma unroll 2
    for (int ii = 0; ii < IPW; ii++) {
        int il = w * IPW + ii;
        const float4* row = up + (size_t)(i0 + il) * (NO * ND / 4) + lane * (ND / 4);
        float4 a0 = row[0], a1 = row[1], a2 = row[2], a3 = row[3];
        float va[16] = {a0.x, a0.y, a0.z, a0.w, a1.x, a1.y, a1.z, a1.w,
                        a2.x, a2.y, a2.z, a2.w, a3.x, a3.y, a3.z, a3.w};
        float dotv = 0.f;
#pragma unroll
        for (int d = 0; d < 16; d++) dotv += sv[d * NO + lane] * va[d];
        tile[il][lane] = -dotv;
    }
    __syncthreads();

    // Transposed, coalesced store: 768B contiguous per (o, i-block)
    for (int idx = threadIdx.x; idx < IPB * NO; idx += 256) {
        int o = idx / IPB;
        int il = idx - o * IPB;
        g_losses[((size_t)(b * NO + o)) * NI + i0 + il] = tile[il][o];
    }
}

__device__ __forceinline__ unsigned mono_key(float f) {
    unsigned x = __float_as_uint(f);
    return (x & 0x80000000u) ? ~x : (x | 0x80000000u);
}

// ---------------------------------------------------------------------------
// Fused select + fixup: ONE 128-THREAD BLOCK per (b,o) (4 warps cooperate).
// Hi16 keys in smem; rounds 3-4 via rare predicated global reloads.
// Warp-aggregated reject-list build; 4-DEEP batched gather (128 capsules in
// flight per block); cross-warp smem reduce.
// ---------------------------------------------------------------------------
__global__ void __launch_bounds__(128) k_selectfix(const float* __restrict__ u,
                                                  float* __restrict__ out) {
    __shared__ unsigned short shi[NI];   // 2304 B
    __shared__ int hist[256];            // 1024 B
    __shared__ short wlist[MAXREJ];      //  464 B
    __shared__ int wcount;
    __shared__ int s_bucket, s_k;
    __shared__ float sred[4][20];

    int bo = blockIdx.x;
    int b = bo >> 5, o = bo & 31;
    int tid = threadIdx.x;
    int w = tid >> 5, lane = tid & 31;

    const float* lp = &g_losses[(size_t)bo * NI];
    hist[tid] = 0; hist[tid + 128] = 0;
    if (tid == 0) { wcount = 0; s_k = KSUB; }
    __syncthreads();

    // ---- Load keys; stash hi16; histogram top byte (round 1)
#pragma unroll
    for (int j = 0; j < KPT; j++) {
        unsigned kk = mono_key(lp[j * 128 + tid]);
        shi[j * 128 + tid] = (unsigned short)(kk >> 16);
        atomicAdd(&hist[kk >> 24], 1);
    }
    __syncthreads();

    // pick round 1 (warp 0)
    if (w == 0) {
        int k = s_k;
        int h[8], seg = 0;
#pragma unroll
        for (int t = 0; t < 8; t++) { h[t] = hist[lane * 8 + t]; seg += h[t]; }
        int incl = seg;
#pragma unroll
        for (int off = 1; off < 32; off <<= 1) {
            int n_ = __shfl_up_sync(0xffffffffu, incl, off);
            if (lane >= off) incl += n_;
        }
        int excl = incl - seg;
        bool has = (excl < k) && (excl + seg >= k);
        unsigned mba = __ballot_sync(0xffffffffu, has);
        int src = __ffs(mba) - 1;
        if (lane == src) {
            int run = excl;
#pragma unroll
            for (int t = 0; t < 8; t++) {
                if (run + h[t] >= k) { s_bucket = lane * 8 + t; s_k = k - run; break; }
                run += h[t];
            }
        }
    }
    __syncthreads();
    unsigned b1 = (unsigned)s_bucket;
    hist[tid] = 0; hist[tid + 128] = 0;
    __syncthreads();

    // ---- Round 2: second byte over hi16 in smem
#pragma unroll
    for (int j = 0; j < KPT; j++) {
        unsigned h16 = shi[j * 128 + tid];
        if ((h16 >> 8) == b1) atomicAdd(&hist[h16 & 255], 1);
    }
    __syncthreads();
    if (w == 0) {
        int k = s_k;
        int h[8], seg = 0;
#pragma unroll
        for (int t = 0; t < 8; t++) { h[t] = hist[lane * 8 + t]; seg += h[t]; }
        int incl = seg;
#pragma unroll
        for (int off = 1; off < 32; off <<= 1) {
            int n_ = __shfl_up_sync(0xffffffffu, incl, off);
            if (lane >= off) incl += n_;
        }
        int excl = incl - seg;
        bool has = (excl < k) && (excl + seg >= k);
        unsigned mba = __ballot_sync(0xffffffffu, has);
        int src = __ffs(mba) - 1;
        if (lane == src) {
            int run = excl;
#pragma unroll
            for (int t = 0; t < 8; t++) {
                if (run + h[t] >= k) { s_bucket = lane * 8 + t; s_k = k - run; break; }
                run += h[t];
            }
        }
    }
    __syncthreads();
    unsigned prefix16 = (b1 << 8) | (unsigned)s_bucket;
    hist[tid] = 0; hist[tid + 128] = 0;
    __syncthreads();

    // ---- Round 3: byte 1 via predicated global reload (few matches, L2-hot)
#pragma unroll
    for (int j = 0; j < KPT; j++) {
        if (shi[j * 128 + tid] == prefix16) {
            unsigned kk = mono_key(lp[j * 128 + tid]);
            atomicAdd(&hist[(kk >> 8) & 255], 1);
        }
    }
    __syncthreads();
    if (w == 0) {
        int k = s_k;
        int h[8], seg = 0;
#pragma unroll
        for (int t = 0; t < 8; t++) { h[t] = hist[lane * 8 + t]; seg += h[t]; }
        int incl = seg;
#pragma unroll
        for (int off = 1; off < 32; off <<= 1) {
            int n_ = __shfl_up_sync(0xffffffffu, incl, off);
            if (lane >= off) incl += n_;
        }
        int excl = incl - seg;
        bool has = (excl < k) && (excl + seg >= k);
        unsigned mba = __ballot_sync(0xffffffffu, has);
        int src = __ffs(mba) - 1;
        if (lane == src) {
            int run = excl;
#pragma unroll
            for (int t = 0; t < 8; t++) {
                if (run + h[t] >= k) { s_bucket = lane * 8 + t; s_k = k - run; break; }
                run += h[t];
            }
        }
    }
    __syncthreads();
    unsigned prefix24 = (prefix16 << 8) | (unsigned)s_bucket;
    hist[tid] = 0; hist[tid + 128] = 0;
    __syncthreads();

    // ---- Round 4: low byte
#pragma unroll
    for (int j = 0; j < KPT; j++) {
        if (shi[j * 128 + tid] == prefix16) {
            unsigned kk = mono_key(lp[j * 128 + tid]);
            if ((kk >> 8) == prefix24) atomicAdd(&hist[kk & 255], 1);
        }
    }
    __syncthreads();
    if (w == 0) {
        int k = s_k;
        int h[8], seg = 0;
#pragma unroll
        for (int t = 0; t < 8; t++) { h[t] = hist[lane * 8 + t]; seg += h[t]; }
        int incl = seg;
#pragma unroll
        for (int off = 1; off < 32; off <<= 1) {
            int n_ = __shfl_up_sync(0xffffffffu, incl, off);
            if (lane >= off) incl += n_;
        }
        int excl = incl - seg;
        bool has = (excl < k) && (excl + seg >= k);
        unsigned mba = __ballot_sync(0xffffffffu, has);
        int src = __ffs(mba) - 1;
        if (lane == src) {
            int run = excl;
#pragma unroll
            for (int t = 0; t < 8; t++) {
                if (run + h[t] >= k) { s_bucket = lane * 8 + t; break; }
                run += h[t];
            }
        }
    }
    __syncthreads();
    unsigned thrkey = (prefix24 << 8) | (unsigned)s_bucket;  // exact k-th key

    // ---- Rejected list: warp-aggregated (1 atomic per warp per sweep step)
#pragma unroll
    for (int j = 0; j < KPT; j++) {
        unsigned h16 = shi[j * 128 + tid];
        bool rej;
        if (h16 > prefix16) rej = true;
        else if (h16 < prefix16) rej = false;
        else rej = (mono_key(lp[j * 128 + tid]) > thrkey);
        unsigned mba = __ballot_sync(0xffffffffu, rej);
        int cnt = __popc(mba);
        int base = 0;
        if (lane == 0 && cnt) base = atomicAdd(&wcount, cnt);
        base = __shfl_sync(0xffffffffu, base, 0);
        if (rej) {
            int pos = base + __popc(mba & ((1u << lane) - 1u));
            wlist[pos] = (short)(j * 128 + tid);
        }
    }
    __syncthreads();
    int nr = wcount;  // <= 230

    // ---- Gather: 4 lanes/capsule, 4-deep batched -> 128 capsules in flight
    int p = tid & 3, g = tid >> 2;  // g in 0..31
    const float4* up = (const float4*)u + (size_t)b * NI * 128 + o * 4 + p;
    float acc0 = 0.f, acc1 = 0.f, acc2 = 0.f, acc3 = 0.f, aden = 0.f;
    int nrp = (nr + 127) & ~127;    // round to 4*32 capsules (max 2 iterations)
    for (int t = g; t < nrp; t += 128) {
        float4 a[4];
#pragma unroll
        for (int q = 0; q < 4; q++) {
            int tq = t + 32 * q;
            bool v = tq < nr;
            int i = v ? (int)wlist[tq] : 0;
            a[q] = up[(size_t)i * 128];
            if (!v) { a[q].x = 0.f; a[q].y = 0.f; a[q].z = 0.f; a[q].w = 0.f; }
        }
#pragma unroll
        for (int q = 0; q < 4; q++) {
            float s = a[q].x * a[q].x + a[q].y * a[q].y
                    + a[q].z * a[q].z + a[q].w * a[q].w;
            s += __shfl_xor_sync(0xffffffffu, s, 1);
            s += __shfl_xor_sync(0xffffffffu, s, 2);
            float n = sqrtf(s);
            acc0 += a[q].x * n; acc1 += a[q].y * n;
            acc2 += a[q].z * n; acc3 += a[q].w * n;
            if (p == 0) aden += n;
        }
    }
    // intra-warp reduce across the 8 quads (offsets 4,8,16 preserve p)
#pragma unroll
    for (int off = 4; off < 32; off <<= 1) {
        acc0 += __shfl_xor_sync(0xffffffffu, acc0, off);
        acc1 += __shfl_xor_sync(0xffffffffu, acc1, off);
        acc2 += __shfl_xor_sync(0xffffffffu, acc2, off);
        acc3 += __shfl_xor_sync(0xffffffffu, acc3, off);
    }
#pragma unroll
    for (int off = 1; off < 32; off <<= 1)
        aden += __shfl_xor_sync(0xffffffffu, aden, off);
    // cross-warp reduce via smem. Writer lane p (lanes 0..3) holds elements
    // 4p..4p+3 in acc0..3  ->  sred[w][4p + c] = element 4p + c = element idx.
    if (lane < 4) {
        sred[w][lane * 4 + 0] = acc0;
        sred[w][lane * 4 + 1] = acc1;
        sred[w][lane * 4 + 2] = acc2;
        sred[w][lane * 4 + 3] = acc3;
    }
    if (lane == 0) sred[w][16] = aden;
    __syncthreads();
    if (tid < 17) {
        float s = sred[0][tid] + sred[1][tid] + sred[2][tid] + sred[3][tid];
        sred[0][tid] = s;
    }
    __syncthreads();
    if (tid < ND) {
        float sub = sred[0][tid];   // element tid directly
        float den2 = g_den[bo] - sred[0][16];
        out[bo * ND + tid] = (g_num[bo * ND + tid] - sub) / den2;
    }
}

extern "C" void kernel_launch(void* const* d_in, const int* in_sizes, int n_in,
                              void* d_out, int out_size) {
    const float* u = (const float*)d_in[0];
    float* out = (float*)d_out;

    k_zero<<<(NB * NO * ND + 255) / 256, 256>>>();
    k_pass1<<<NB * CHUNKS, 256>>>(u);
    k_pass2<<<NB * CHUNKS, 256>>>(u);
    k_selectfix<<<NB * NO, 128>>>(u, out);
}

// round 15
// speedup vs baseline: 1.1337x; 1.1337x over previous
#include <cuda_runtime.h>
#include <math.h>

// Problem constants
#define NB 128
#define NI 1152
#define NO 32
#define ND 16
#define KSUB 922          // ceil(0.8 * 1152)
#define CHUNKS 9
#define IPB (NI / CHUNKS) // 128 i's per block (pass1)
#define IPW (IPB / 8)     // 16 i's per warp
#define MAXREJ 232        // >= NI - KSUB = 230
#define ROWK 1153         // key row stride in words (odd -> conflict-free)
#define ROWH 257          // hist row stride in words (odd -> conflict-free)

// Scratch (no allocation allowed -> __device__ globals)
__device__ float g_num[NB * NO * ND];
__device__ float g_den[NB * NO];

__global__ void k_zero() {
    int idx = blockIdx.x * blockDim.x + threadIdx.x;
    if (idx < NB * NO * ND) g_num[idx] = 0.f;
    if (idx < NB * NO)      g_den[idx] = 0.f;
}

// ---------------------------------------------------------------------------
// Pass 1: n = ||u||, num = sum_i u*n, den = sum_i n  (per b,o)
// ---------------------------------------------------------------------------
__global__ void __launch_bounds__(256) k_pass1(const float* __restrict__ u) {
    int b = blockIdx.x / CHUNKS;
    int chunk = blockIdx.x % CHUNKS;
    int w = threadIdx.x >> 5;
    int lane = threadIdx.x & 31;

    const float4* up = (const float4*)u + (size_t)b * NI * (NO * ND / 4);
    float acc[ND];
    float accden = 0.f;
#pragma unroll
    for (int d = 0; d < ND; d++) acc[d] = 0.f;

    int i0 = chunk * IPB + w * IPW;
#pragma unroll 2
    for (int ii = 0; ii < IPW; ii++) {
        const float4* row = up + (size_t)(i0 + ii) * (NO * ND / 4) + lane * (ND / 4);
        float4 a0 = row[0], a1 = row[1], a2 = row[2], a3 = row[3];
        float va[16] = {a0.x, a0.y, a0.z, a0.w, a1.x, a1.y, a1.z, a1.w,
                        a2.x, a2.y, a2.z, a2.w, a3.x, a3.y, a3.z, a3.w};
        float s = 0.f;
#pragma unroll
        for (int d = 0; d < 16; d++) s += va[d] * va[d];
        float n = sqrtf(s);
#pragma unroll
        for (int d = 0; d < 16; d++) acc[d] += va[d] * n;
        accden += n;
    }

    __shared__ float snum[8][NO * ND];
    __shared__ float sden[8][NO];
#pragma unroll
    for (int d = 0; d < ND; d++) snum[w][d * NO + lane] = acc[d];
    sden[w][lane] = accden;
    __syncthreads();

    for (int idx = threadIdx.x; idx < NO * ND; idx += 256) {
        int d = idx / NO, o = idx % NO;
        float s = 0.f;
#pragma unroll
        for (int ww = 0; ww < 8; ww++) s += snum[ww][idx];
        atomicAdd(&g_num[b * NO * ND + o * ND + d], s);
    }
    if (threadIdx.x < NO) {
        float s = 0.f;
#pragma unroll
        for (int ww = 0; ww < 8; ww++) s += sden[ww][threadIdx.x];
        atomicAdd(&g_den[b * NO + threadIdx.x], s);
    }
}

__device__ __forceinline__ unsigned mono_key(float f) {
    unsigned x = __float_as_uint(f);
    return (x & 0x80000000u) ? ~x : (x | 0x80000000u);
}

// Warp pick: 256-bin hist row -> bucket containing rank k; updates k.
__device__ __forceinline__ unsigned warp_pick(const int* oh, int lane, int& k) {
    int h[8], seg = 0;
#pragma unroll
    for (int t = 0; t < 8; t++) { h[t] = oh[lane * 8 + t]; seg += h[t]; }
    int incl = seg;
#pragma unroll
    for (int off = 1; off < 32; off <<= 1) {
        int n_ = __shfl_up_sync(0xffffffffu, incl, off);
        if (lane >= off) incl += n_;
    }
    int excl = incl - seg;
    bool has = (excl < k) && (excl + seg >= k);
    unsigned mba = __ballot_sync(0xffffffffu, has);
    int src = __ffs(mba) - 1;
    int bsel = 0, kk2 = 0;
    if (lane == src) {
        int run = excl;
#pragma unroll
        for (int t = 0; t < 8; t++) {
            if (run + h[t] >= k) { bsel = lane * 8 + t; kk2 = k - run; break; }
            run += h[t];
        }
    }
    bsel = __shfl_sync(0xffffffffu, bsel, src);
    k = __shfl_sync(0xffffffffu, kk2, src);
    return (unsigned)bsel;
}

// ---------------------------------------------------------------------------
// Fused pass2 + select + fixup: ONE 1024-thread block per batch b.
// Streams u[b] once (losses -> full 32-bit keys in SMEM, no global array),
// then warp w selects + gathers for o = w, entirely warp-private, with the
// gather hitting L2-hot u. Writes the output directly.
// ---------------------------------------------------------------------------
__global__ void __launch_bounds__(1024) k_pass2sel(const float* __restrict__ u,
                                                   float* __restrict__ out) {
    extern __shared__ char smem[];
    float*    sv    = (float*)smem;                       //  2048 B  sv[d*32+o]
    unsigned* keys  = (unsigned*)(sv + 512);              // 32*1153*4 = 147584 B
    int*      hist  = (int*)(keys + 32 * ROWK);           // 32*257*4  =  32896 B
    short*    wlist = (short*)(hist + 32 * ROWH);         // 32*232*2  =  14848 B

    int b = blockIdx.x;
    int tid = threadIdx.x;
    int w = tid >> 5, lane = tid & 31;

    // v[b] into smem (transposed), zero hist
    for (int idx = tid; idx < NO * ND; idx += 1024) {
        int o = idx / ND, d = idx % ND;
        sv[d * NO + o] = g_num[b * NO * ND + idx] / g_den[b * NO + o];
    }
    for (int idx = tid; idx < 32 * ROWH; idx += 1024) hist[idx] = 0;
    __syncthreads();

    // ---- Sweep: warp w handles i = w + 32*s. Lane = o. Keys + round-1 hist.
    const float4* up = (const float4*)u + (size_t)b * NI * 128;
#pragma unroll 2
    for (int s = 0; s < NI / 32; s++) {
        int i = w + (s << 5);
        const float4* row = up + (size_t)i * 128 + lane * 4;
        float4 a0 = row[0], a1 = row[1], a2 = row[2], a3 = row[3];
        float va[16] = {a0.x, a0.y, a0.z, a0.w, a1.x, a1.y, a1.z, a1.w,
                        a2.x, a2.y, a2.z, a2.w, a3.x, a3.y, a3.z, a3.w};
        float dotv = 0.f;
#pragma unroll
        for (int d = 0; d < 16; d++) dotv += sv[d * NO + lane] * va[d];
        unsigned kk = mono_key(-dotv);
        keys[lane * ROWK + i] = kk;
        atomicAdd(&hist[lane * ROWH + (kk >> 24)], 1);
    }
    __syncthreads();

    // ---- Per-warp selection for o = w (warp-private; __syncwarp only)
    unsigned* mk = keys + w * ROWK;
    int* oh = hist + w * ROWH;

    int k = KSUB;
    unsigned b1 = warp_pick(oh, lane, k);

    // round 2
#pragma unroll
    for (int t = 0; t < 8; t++) oh[lane * 8 + t] = 0;
    __syncwarp();
#pragma unroll 4
    for (int j = 0; j < NI / 32; j++) {
        unsigned kk = mk[j * 32 + lane];
        if ((kk >> 24) == b1) atomicAdd(&oh[(kk >> 16) & 255], 1);
    }
    __syncwarp();
    unsigned b2 = warp_pick(oh, lane, k);
    unsigned prefix16 = (b1 << 8) | b2;

    // round 3
#pragma unroll
    for (int t = 0; t < 8; t++) oh[lane * 8 + t] = 0;
    __syncwarp();
#pragma unroll 4
    for (int j = 0; j < NI / 32; j++) {
        unsigned kk = mk[j * 32 + lane];
        if ((kk >> 16) == prefix16) atomicAdd(&oh[(kk >> 8) & 255], 1);
    }
    __syncwarp();
    unsigned b3 = warp_pick(oh, lane, k);
    unsigned prefix24 = (prefix16 << 8) | b3;

    // round 4
#pragma unroll
    for (int t = 0; t < 8; t++) oh[lane * 8 + t] = 0;
    __syncwarp();
#pragma unroll 4
    for (int j = 0; j < NI / 32; j++) {
        unsigned kk = mk[j * 32 + lane];
        if ((kk >> 8) == prefix24) atomicAdd(&oh[kk & 255], 1);
    }
    __syncwarp();
    unsigned b4 = warp_pick(oh, lane, k);
    unsigned thrkey = (prefix24 << 8) | b4;   // exact k-th smallest key

    // ---- Rejected list (key > thrkey), atomic-free warp compaction
    short* wl = wlist + w * MAXREJ;
    int base = 0;
#pragma unroll 4
    for (int j = 0; j < NI / 32; j++) {
        bool rej = mk[j * 32 + lane] > thrkey;
        unsigned mba = __ballot_sync(0xffffffffu, rej);
        if (rej) wl[base + __popc(mba & ((1u << lane) - 1u))] =
            (short)(j * 32 + lane);
        base += __popc(mba);
    }
    int nr = base;  // <= 230
    __syncwarp();

    // ---- Gather rejected capsules (L2-hot), 4 lanes/capsule, 2-deep batch
    int p = lane & 3, g = lane >> 2;
    const float4* gp = up + w * 4 + p;
    float acc0 = 0.f, acc1 = 0.f, acc2 = 0.f, acc3 = 0.f, aden = 0.f;
    int nrp = (nr + 15) & ~15;
    for (int t = g; t < nrp; t += 16) {
        int t2 = t + 8;
        bool v1 = t < nr, v2 = t2 < nr;
        int i1 = v1 ? (int)wl[t] : 0;
        int i2 = v2 ? (int)wl[t2] : 0;
        float4 a = gp[(size_t)i1 * 128];
        float4 c = gp[(size_t)i2 * 128];
        if (!v1) { a.x = 0.f; a.y = 0.f; a.z = 0.f; a.w = 0.f; }
        if (!v2) { c.x = 0.f; c.y = 0.f; c.z = 0.f; c.w = 0.f; }
        float s1 = a.x * a.x + a.y * a.y + a.z * a.z + a.w * a.w;
        float s2 = c.x * c.x + c.y * c.y + c.z * c.z + c.w * c.w;
        s1 += __shfl_xor_sync(0xffffffffu, s1, 1);
        s2 += __shfl_xor_sync(0xffffffffu, s2, 1);
        s1 += __shfl_xor_sync(0xffffffffu, s1, 2);
        s2 += __shfl_xor_sync(0xffffffffu, s2, 2);
        float n1 = sqrtf(s1), n2 = sqrtf(s2);
        acc0 += a.x * n1 + c.x * n2;
        acc1 += a.y * n1 + c.y * n2;
        acc2 += a.z * n1 + c.z * n2;
        acc3 += a.w * n1 + c.w * n2;
        if (p == 0) aden += n1 + n2;
    }
    // reduce across the 8 quads (offsets 4,8,16 preserve p)
#pragma unroll
    for (int off = 4; off < 32; off <<= 1) {
        acc0 += __shfl_xor_sync(0xffffffffu, acc0, off);
        acc1 += __shfl_xor_sync(0xffffffffu, acc1, off);
        acc2 += __shfl_xor_sync(0xffffffffu, acc2, off);
        acc3 += __shfl_xor_sync(0xffffffffu, acc3, off);
    }
#pragma unroll
    for (int off = 1; off < 32; off <<= 1)
        aden += __shfl_xor_sync(0xffffffffu, aden, off);

    // lanes 0..3 (p = lane) hold elements 4p..4p+3 -> one float4 each
    if (lane < 4) {
        int bo = b * NO + w;
        float4 nm = ((const float4*)g_num)[bo * 4 + lane];
        float den2 = g_den[bo] - aden;
        float4 r;
        r.x = (nm.x - acc0) / den2;
        r.y = (nm.y - acc1) / den2;
        r.z = (nm.z - acc2) / den2;
        r.w = (nm.w - acc3) / den2;
        ((float4*)out)[bo * 4 + lane] = r;
    }
}

#define SMEM_P2S (512 * 4 + 32 * ROWK * 4 + 32 * ROWH * 4 + 32 * MAXREJ * 2)

extern "C" void kernel_launch(void* const* d_in, const int* in_sizes, int n_in,
                              void* d_out, int out_size) {
    const float* u = (const float*)d_in[0];
    float* out = (float*)d_out;

    cudaFuncSetAttribute(k_pass2sel,
                         cudaFuncAttributeMaxDynamicSharedMemorySize, SMEM_P2S);

    k_zero<<<(NB * NO * ND + 255) / 256, 256>>>();
    k_pass1<<<NB * CHUNKS, 256>>>(u);
    k_pass2sel<<<NB, 1024, SMEM_P2S>>>(u, out);
}